// round 15
// baseline (speedup 1.0000x reference)
#include <cuda_runtime.h>
#include <cuda_bf16.h>
#include <math.h>
#include <stdint.h>

// ---------------- problem constants ----------------
#define B_      16
#define S_      576
#define F_      700
#define D_      64
#define KC_     1024
#define T_      (B_*S_)         // 9216 tokens
#define H1_     512
#define H2_     256
#define ENC_    128             // 2*D
#define SF_     (S_*F_)         // 403200
#define SD_     (S_*D_)         // 36864

#define OUT_REC  0
#define OUT_MEAN (B_*SF_)
#define OUT_LV   (OUT_MEAN + T_*D_)
#define OUT_VQL  (OUT_LV + T_*D_)

#define DEC1_CHUNKS 144
#define NCB         2            // candidate blocks (vq grid.x)
#define VQ_CB       4            // codebook col-blocks per vq CTA

typedef unsigned long long u64;
typedef __nv_bfloat16 bf16;

// ---------------- scratch (device globals; no allocation allowed) ----------------
__device__ __align__(256) float g_h1[T_*H1_];
__device__ __align__(256) float g_h2[T_*H2_];
__device__ __align__(256) float g_ze[T_*D_];
__device__ __align__(256) float g_csq[KC_];
__device__ __align__(256) float g_tokloss[T_];
__device__ __align__(256) float g_dpart[DEC1_CHUNKS*16*H2_];
__device__ __align__(256) float g_dvec[16*H2_];
__device__ __align__(256) float g_wt1[H1_*F_];
__device__ __align__(256) float g_wt2[H2_*H1_];
__device__ __align__(256) float g_wt3[ENC_*H2_];
__device__ __align__(256) float g_candD[NCB*T_];
__device__ __align__(256) int   g_candI[NCB*T_];

// ---------------- f32x2 helpers (decoder kernels) ----------------
__device__ __forceinline__ u64 dupf(float a) {
    unsigned r = __float_as_uint(a);
    u64 d;
    asm("mov.b64 %0, {%1, %1};" : "=l"(d) : "r"(r));
    return d;
}
__device__ __forceinline__ void ffma2(u64 &d, u64 a, u64 b) {
    asm("fma.rn.f32x2 %0, %1, %2, %0;" : "+l"(d) : "l"(a), "l"(b));
}
__device__ __forceinline__ float2 unpk(u64 v) {
    unsigned lo, hi;
    asm("mov.b64 {%0, %1}, %2;" : "=r"(lo), "=r"(hi) : "l"(v));
    return make_float2(__uint_as_float(lo), __uint_as_float(hi));
}
__device__ __forceinline__ float softplusf(float x) {
    return fmaxf(x, 0.0f) + log1pf(expf(-fabsf(x)));
}

// ---------------- mma.sync helpers ----------------
__device__ __forceinline__ uint32_t smem_u32(const void* p) {
    uint32_t a;
    asm("{ .reg .u64 t; cvta.to.shared.u64 t, %1; cvt.u32.u64 %0, t; }" : "=r"(a) : "l"(p));
    return a;
}
__device__ __forceinline__ void ldsm4(uint32_t (&r)[4], uint32_t addr) {
    asm volatile("ldmatrix.sync.aligned.m8n8.x4.shared.b16 {%0,%1,%2,%3}, [%4];"
                 : "=r"(r[0]), "=r"(r[1]), "=r"(r[2]), "=r"(r[3]) : "r"(addr));
}
__device__ __forceinline__ void mma_bf16(float (&d)[4], const uint32_t (&a)[4],
                                         uint32_t b0, uint32_t b1) {
    asm volatile("mma.sync.aligned.m16n8k16.row.col.f32.bf16.bf16.f32 "
                 "{%0,%1,%2,%3}, {%4,%5,%6,%7}, {%8,%9}, {%0,%1,%2,%3};"
                 : "+f"(d[0]), "+f"(d[1]), "+f"(d[2]), "+f"(d[3])
                 : "r"(a[0]), "r"(a[1]), "r"(a[2]), "r"(a[3]), "r"(b0), "r"(b1));
}
// split fp32 pair -> packed bf16x2 hi and lo
__device__ __forceinline__ void split2(float x, float y, uint32_t &hi, uint32_t &lo) {
    __nv_bfloat162 h = __floats2bfloat162_rn(x, y);
    float hx = __bfloat162float(h.x), hy = __bfloat162float(h.y);
    __nv_bfloat162 l = __floats2bfloat162_rn(x - hx, y - hy);
    hi = *reinterpret_cast<uint32_t*>(&h);
    lo = *reinterpret_cast<uint32_t*>(&l);
}

// SMEM per stage: 20480 bf16 elems (40960 B): Ah[128][40] | Al +5120 | Bh +10240 | Bl +15360
#define STAGE_E   20480
#define NSTG      3
#define SMEM_BYTES (NSTG * STAGE_E * 2)

// ---------------- bf16x3 tensor-core GEMM, 3-buffer single-sync pipeline ---------
// MODE 1: relu+bias fp32 out.  MODE 5: encoder head — fused bias + reparam epilogue.
template<int MODE>
__global__ __launch_bounds__(256, 1) void mma_gemm(
    int M, int N, int K,
    const float* __restrict__ A, const float* __restrict__ Bt,
    const float* __restrict__ bias, float* __restrict__ C,
    const float* __restrict__ ep, float* __restrict__ outp)
{
    extern __shared__ __align__(16) __nv_bfloat16 sm[];
    const int tid  = threadIdx.x;
    const int wid  = tid >> 5;
    const int lane = tid & 31;
    const int row0 = blockIdx.y * 128;
    const int col0 = blockIdx.x * 128;
    const int NS = (K + 31) >> 5;
    const uint32_t smb = smem_u32(sm);

    float acc[2][8][4];
#pragma unroll
    for (int mt = 0; mt < 2; ++mt)
#pragma unroll
        for (int nt = 0; nt < 8; ++nt)
#pragma unroll
            for (int q = 0; q < 4; ++q) acc[mt][nt][q] = 0.0f;

    const int lrow = tid >> 3;        // 0..31 base row (with +32*i)
    const int lc4  = tid & 7;         // float4 col within BK

    float4 pa[4], pb[4];

    auto fetch = [&](int k0) {
#pragma unroll
        for (int i = 0; i < 4; ++i) {
            int row = lrow + i * 32;
            int kk  = k0 + lc4 * 4;
            if (kk < K) {
                pa[i] = *(const float4*)(A  + (size_t)(row0 + row) * K + kk);
                pb[i] = *(const float4*)(Bt + (size_t)(col0 + row) * K + kk);
            } else {
                pa[i] = make_float4(0.f, 0.f, 0.f, 0.f);
                pb[i] = make_float4(0.f, 0.f, 0.f, 0.f);
            }
        }
    };

    auto store_to = [&](int slot) {
        uint32_t stg = (uint32_t)slot * STAGE_E;
#pragma unroll
        for (int i = 0; i < 4; ++i) {
            int row = lrow + i * 32;
            uint32_t off = stg + row * 40 + lc4 * 4;
            uint32_t h0, l0, h1, l1;
            split2(pa[i].x, pa[i].y, h0, l0);
            split2(pa[i].z, pa[i].w, h1, l1);
            *(uint2*)&sm[off]          = make_uint2(h0, h1);
            *(uint2*)&sm[off + 5120]   = make_uint2(l0, l1);
            split2(pb[i].x, pb[i].y, h0, l0);
            split2(pb[i].z, pb[i].w, h1, l1);
            *(uint2*)&sm[off + 10240]  = make_uint2(h0, h1);
            *(uint2*)&sm[off + 15360]  = make_uint2(l0, l1);
        }
    };

    const int wm = wid >> 1, wn = wid & 1;
    const int arow  = wm * 32 + (lane & 15);
    const int acolB = (lane >> 4) * 16;
    const int brow  = wn * 64 + ((lane >> 4) << 3) + (lane & 7);
    const int bkhB  = ((lane >> 3) & 1) * 16;

    auto compute = [&](int slot) {
        const uint32_t stgB = (uint32_t)slot * (STAGE_E * 2);
#pragma unroll
        for (int ks = 0; ks < 2; ++ks) {
            uint32_t ah[2][4], al[2][4];
#pragma unroll
            for (int mt = 0; mt < 2; ++mt) {
                uint32_t addr = smb + stgB + (uint32_t)(arow + mt * 16) * 80u
                              + (uint32_t)ks * 32u + acolB;
                ldsm4(ah[mt], addr);
                ldsm4(al[mt], addr + 10240u);
            }
            uint32_t bh[8][2], bl[8][2];
#pragma unroll
            for (int p = 0; p < 4; ++p) {
                uint32_t addr = smb + stgB + 20480u + (uint32_t)(brow + p * 16) * 80u
                              + (uint32_t)ks * 32u + bkhB;
                uint32_t r[4];
                ldsm4(r, addr);
                bh[2*p][0] = r[0]; bh[2*p][1] = r[1];
                bh[2*p+1][0] = r[2]; bh[2*p+1][1] = r[3];
                ldsm4(r, addr + 10240u);
                bl[2*p][0] = r[0]; bl[2*p][1] = r[1];
                bl[2*p+1][0] = r[2]; bl[2*p+1][1] = r[3];
            }
#pragma unroll
            for (int mt = 0; mt < 2; ++mt)
#pragma unroll
                for (int nt = 0; nt < 8; ++nt) {
                    mma_bf16(acc[mt][nt], ah[mt], bh[nt][0], bh[nt][1]);
                    mma_bf16(acc[mt][nt], ah[mt], bl[nt][0], bl[nt][1]);
                    mma_bf16(acc[mt][nt], al[mt], bh[nt][0], bh[nt][1]);
                }
        }
    };

    fetch(0);
    store_to(0);
    if (NS > 1) fetch(32);

    int scur = 0, sst = 1;
    for (int s = 0; s < NS; ++s) {
        __syncthreads();
        if (s + 1 < NS) store_to(sst);
        if (s + 2 < NS) fetch((s + 2) * 32);
        compute(scur);
        scur = (scur + 1 == NSTG) ? 0 : scur + 1;
        sst  = (sst  + 1 == NSTG) ? 0 : sst  + 1;
    }

    // ---- epilogue ----
    if (MODE == 5) {
        __syncthreads();
        float* smf = (float*)sm;       // [128][132]
#pragma unroll
        for (int mt = 0; mt < 2; ++mt) {
            int r = wm * 32 + mt * 16 + (lane >> 2);
#pragma unroll
            for (int nt = 0; nt < 8; ++nt) {
                int c = wn * 64 + nt * 8 + (lane & 3) * 2;
                float b0 = bias[c], b1 = bias[c + 1];
                smf[r * 132 + c]           = acc[mt][nt][0] + b0;
                smf[r * 132 + c + 1]       = acc[mt][nt][1] + b1;
                smf[(r + 8) * 132 + c]     = acc[mt][nt][2] + b0;
                smf[(r + 8) * 132 + c + 1] = acc[mt][nt][3] + b1;
            }
        }
        __syncthreads();
#pragma unroll
        for (int it = 0; it < 32; ++it) {
            int idx = it * 256 + tid;          // 0..8191
            int r = idx >> 6, d = idx & 63;
            float m  = smf[r * 132 + d];
            float lv = smf[r * 132 + 64 + d];
            int gi = (row0 + r) * 64 + d;
            float zv = m + expf(0.5f * lv) * ep[gi];
            g_ze[gi] = zv;
            outp[OUT_MEAN + gi] = m;
            outp[OUT_LV + gi]   = lv;
        }
        return;
    }

#pragma unroll
    for (int mt = 0; mt < 2; ++mt) {
        int r = row0 + wm * 32 + mt * 16 + (lane >> 2);
#pragma unroll
        for (int nt = 0; nt < 8; ++nt) {
            int c = col0 + wn * 64 + nt * 8 + (lane & 3) * 2;
            float b0 = bias[c], b1 = bias[c + 1];
            float v0 = fmaxf(acc[mt][nt][0] + b0, 0.0f);
            float v1 = fmaxf(acc[mt][nt][1] + b1, 0.0f);
            float v2 = fmaxf(acc[mt][nt][2] + b0, 0.0f);
            float v3 = fmaxf(acc[mt][nt][3] + b1, 0.0f);
            *(float2*)&C[(size_t)r * N + c]       = make_float2(v0, v1);
            *(float2*)&C[(size_t)(r + 8) * N + c] = make_float2(v2, v3);
        }
    }
}

// ---------------- persistent VQ kernel ----------------
__global__ __launch_bounds__(256, 1) void vq_kernel(
    const float* __restrict__ A, const float* __restrict__ cbk)
{
    extern __shared__ __align__(16) __nv_bfloat16 sm[];
    __shared__ float scsq[KC_];
    __shared__ float sdm[256];
    __shared__ int   sim[256];

    const int tid  = threadIdx.x;
    const int wid  = tid >> 5;
    const int lane = tid & 31;
    const int row0 = blockIdx.y * 128;
    const uint32_t smb = smem_u32(sm);

    for (int i = tid; i < KC_; i += 256) scsq[i] = g_csq[i];

    const int lrow = tid >> 3;
    const int lc4  = tid & 7;

    // ---- load A (z_e) tile: 2 k-stages, hi/lo ----
#pragma unroll
    for (int s2 = 0; s2 < 2; ++s2) {
#pragma unroll
        for (int i = 0; i < 4; ++i) {
            int row = lrow + i * 32;
            float4 v = *(const float4*)(A + (size_t)(row0 + row) * 64 + s2 * 32 + lc4 * 4);
            uint32_t h0, l0, h1, l1;
            split2(v.x, v.y, h0, l0);
            split2(v.z, v.w, h1, l1);
            uint32_t off = s2 * 10240 + row * 40 + lc4 * 4;
            *(uint2*)&sm[off]        = make_uint2(h0, h1);
            *(uint2*)&sm[off + 5120] = make_uint2(l0, l1);
        }
    }

    float4 pb[8];
    auto fetchB = [&](int cb) {
        int colcb = (blockIdx.x * VQ_CB + cb) * 128;
#pragma unroll
        for (int i = 0; i < 4; ++i) {
            int row = colcb + lrow + i * 32;
            pb[i]     = *(const float4*)(cbk + (size_t)row * 64 + lc4 * 4);
            pb[4 + i] = *(const float4*)(cbk + (size_t)row * 64 + 32 + lc4 * 4);
        }
    };
    auto storeB = [&](int buf) {
        uint32_t base = 20480 + (uint32_t)buf * 20480;
#pragma unroll
        for (int s2 = 0; s2 < 2; ++s2) {
#pragma unroll
            for (int i = 0; i < 4; ++i) {
                int row = lrow + i * 32;
                float4 v = pb[s2 * 4 + i];
                uint32_t h0, l0, h1, l1;
                split2(v.x, v.y, h0, l0);
                split2(v.z, v.w, h1, l1);
                uint32_t off = base + s2 * 10240 + row * 40 + lc4 * 4;
                *(uint2*)&sm[off]        = make_uint2(h0, h1);
                *(uint2*)&sm[off + 5120] = make_uint2(l0, l1);
            }
        }
    };

    const int wm = wid >> 1, wn = wid & 1;
    const int arow  = wm * 32 + (lane & 15);
    const int acolB = (lane >> 4) * 16;
    const int brow  = wn * 64 + ((lane >> 4) << 3) + (lane & 7);
    const int bkhB  = ((lane >> 3) & 1) * 16;

    fetchB(0);
    storeB(0);
    __syncthreads();

    float rbD[2][2] = {{3.4e38f, 3.4e38f}, {3.4e38f, 3.4e38f}};
    int   rbI[2][2] = {{0x7fffffff, 0x7fffffff}, {0x7fffffff, 0x7fffffff}};

    int buf = 0;
    for (int cb = 0; cb < VQ_CB; ++cb) {
        if (cb + 1 < VQ_CB) fetchB(cb + 1);

        float acc[2][8][4];
#pragma unroll
        for (int mt = 0; mt < 2; ++mt)
#pragma unroll
            for (int nt = 0; nt < 8; ++nt)
#pragma unroll
                for (int q = 0; q < 4; ++q) acc[mt][nt][q] = 0.0f;

        const uint32_t bbase = 40960u + (uint32_t)buf * 40960u;
#pragma unroll
        for (int s2 = 0; s2 < 2; ++s2) {
            const uint32_t aB = (uint32_t)s2 * 20480u;
            const uint32_t bB = bbase + (uint32_t)s2 * 20480u;
#pragma unroll
            for (int ks = 0; ks < 2; ++ks) {
                uint32_t ah[2][4], al[2][4];
#pragma unroll
                for (int mt = 0; mt < 2; ++mt) {
                    uint32_t addr = smb + aB + (uint32_t)(arow + mt * 16) * 80u
                                  + (uint32_t)ks * 32u + acolB;
                    ldsm4(ah[mt], addr);
                    ldsm4(al[mt], addr + 10240u);
                }
                uint32_t bh[8][2], bl[8][2];
#pragma unroll
                for (int p = 0; p < 4; ++p) {
                    uint32_t addr = smb + bB + (uint32_t)(brow + p * 16) * 80u
                                  + (uint32_t)ks * 32u + bkhB;
                    uint32_t r[4];
                    ldsm4(r, addr);
                    bh[2*p][0] = r[0]; bh[2*p][1] = r[1];
                    bh[2*p+1][0] = r[2]; bh[2*p+1][1] = r[3];
                    ldsm4(r, addr + 10240u);
                    bl[2*p][0] = r[0]; bl[2*p][1] = r[1];
                    bl[2*p+1][0] = r[2]; bl[2*p+1][1] = r[3];
                }
#pragma unroll
                for (int mt = 0; mt < 2; ++mt)
#pragma unroll
                    for (int nt = 0; nt < 8; ++nt) {
                        mma_bf16(acc[mt][nt], ah[mt], bh[nt][0], bh[nt][1]);
                        mma_bf16(acc[mt][nt], ah[mt], bl[nt][0], bl[nt][1]);
                        mma_bf16(acc[mt][nt], al[mt], bh[nt][0], bh[nt][1]);
                    }
            }
        }

        int colcb = (blockIdx.x * VQ_CB + cb) * 128;
#pragma unroll
        for (int mt = 0; mt < 2; ++mt) {
#pragma unroll
            for (int rp = 0; rp < 2; ++rp) {
                float best = 3.4e38f; int bidx = 0;
#pragma unroll
                for (int nt = 0; nt < 8; ++nt) {
                    int cg = colcb + wn * 64 + nt * 8 + (lane & 3) * 2;
                    float d0 = scsq[cg]     - 2.0f * acc[mt][nt][rp * 2 + 0];
                    float d1 = scsq[cg + 1] - 2.0f * acc[mt][nt][rp * 2 + 1];
                    if (d0 < best) { best = d0; bidx = cg;     }
                    if (d1 < best) { best = d1; bidx = cg + 1; }
                }
#pragma unroll
                for (int msk = 1; msk <= 2; msk <<= 1) {
                    float od = __shfl_xor_sync(0xffffffffu, best, msk);
                    int   oi = __shfl_xor_sync(0xffffffffu, bidx, msk);
                    if (od < best || (od == best && oi < bidx)) { best = od; bidx = oi; }
                }
                if (best < rbD[mt][rp] || (best == rbD[mt][rp] && bidx < rbI[mt][rp])) {
                    rbD[mt][rp] = best; rbI[mt][rp] = bidx;
                }
            }
        }

        if (cb + 1 < VQ_CB) {
            __syncthreads();
            storeB(buf ^ 1);
            __syncthreads();
            buf ^= 1;
        }
    }

    if ((lane & 3) == 0) {
#pragma unroll
        for (int mt = 0; mt < 2; ++mt)
#pragma unroll
            for (int rp = 0; rp < 2; ++rp) {
                int rl = wm * 32 + mt * 16 + rp * 8 + (lane >> 2);
                sdm[wn * 128 + rl] = rbD[mt][rp];
                sim[wn * 128 + rl] = rbI[mt][rp];
            }
    }
    __syncthreads();
    if (tid < 128) {
        float d0 = sdm[tid], d1 = sdm[128 + tid];
        int   i0 = sim[tid], i1 = sim[128 + tid];
        bool t1 = (d1 < d0) || (d1 == d0 && i1 < i0);
        g_candD[(size_t)blockIdx.x * T_ + row0 + tid] = t1 ? d1 : d0;
        g_candI[(size_t)blockIdx.x * T_ + row0 + tid] = t1 ? i1 : i0;
    }
}

// ---------------- fused prep: 3 weight transposes + codebook sq norms ------------
__device__ __forceinline__ void transpose_tile(const float* __restrict__ W,
                                               float* __restrict__ Wt,
                                               int K, int N, int kb, int nb, int tid)
{
    __shared__ float tile[32][33];
    int tx = tid & 31, ty = tid >> 5;   // 32 x 8
#pragma unroll
    for (int i = 0; i < 32; i += 8) {
        int k = kb + ty + i, n = nb + tx;
        tile[ty + i][tx] = (k < K && n < N) ? W[(size_t)k * N + n] : 0.0f;
    }
    __syncthreads();
#pragma unroll
    for (int i = 0; i < 32; i += 8) {
        int n = nb + ty + i, k = kb + tx;
        if (n < N && k < K) Wt[(size_t)n * K + k] = tile[tx][ty + i];
    }
}

__global__ void prep_kernel(const float* __restrict__ We1, const float* __restrict__ We2,
                            const float* __restrict__ We3, const float* __restrict__ cb)
{
    int bx = blockIdx.x, tid = threadIdx.x;
    if (bx < 352) {               // W1: 16 x 22 tiles
        transpose_tile(We1, g_wt1, F_,  H1_, (bx >> 4) * 32, (bx & 15) * 32, tid);
    } else if (bx < 480) {        // W2: 8 x 16 tiles
        int b = bx - 352;
        transpose_tile(We2, g_wt2, H1_, H2_, (b >> 3) * 32, (b & 7) * 32, tid);
    } else if (bx < 512) {        // W3: 4 x 8 tiles
        int b = bx - 480;
        transpose_tile(We3, g_wt3, H2_, ENC_, (b >> 2) * 32, (b & 3) * 32, tid);
    } else {                      // csq: 4 blocks x 256 codes
        int k = (bx - 512) * 256 + tid;
        const float4* c = (const float4*)cb + k * 16;
        float s = 0.0f;
#pragma unroll
        for (int i = 0; i < 16; ++i) {
            float4 v = c[i];
            s += v.x * v.x + v.y * v.y + v.z * v.z + v.w * v.w;
        }
        g_csq[k] = s;
    }
}

// ---------------- fused VQ-finish + decoder GEMM1 split-K partials ----------------
// CTA c owns K-chunk [256c, 256c+256) = tokens (b, s in [4c, 4c+4)), 64 tokens.
__global__ __launch_bounds__(256) void dec1_vq_kernel(const float* __restrict__ W,
                                                      const float* __restrict__ cbk)
{
    __shared__ __align__(16) float zs[256 * 16];   // zs[kk*16 + b]
    const int c    = blockIdx.x;
    const int k0   = c * 256;
    const int wid  = threadIdx.x >> 5;
    const int lane = threadIdx.x & 31;

    // 64 tokens, 8 warps x 8 iterations
#pragma unroll
    for (int i = 0; i < 8; ++i) {
        int tt = i * 8 + wid;                 // 0..63
        int b = tt >> 2, j = tt & 3;
        int t = b * S_ + 4 * c + j;

        float d = 3.4e38f; int ix = 0x7fffffff;
        if (lane < NCB) {
            d  = g_candD[(size_t)lane * T_ + t];
            ix = g_candI[(size_t)lane * T_ + t];
        }
        {
            float od = __shfl_down_sync(0xffffffffu, d, 1);
            int   oi = __shfl_down_sync(0xffffffffu, ix, 1);
            if (od < d || (od == d && oi < ix)) { d = od; ix = oi; }
        }
        ix = __shfl_sync(0xffffffffu, ix, 0);

        float l = 0.0f;
        if (lane < 16) {
            float4 cv = ((const float4*)cbk)[ix * 16 + lane];
            float4 zv = ((const float4*)g_ze)[t * 16 + lane];
            int kk = j * 64 + lane * 4;
            zs[(kk + 0) * 16 + b] = cv.x;
            zs[(kk + 1) * 16 + b] = cv.y;
            zs[(kk + 2) * 16 + b] = cv.z;
            zs[(kk + 3) * 16 + b] = cv.w;
            float dx = zv.x - cv.x, dy = zv.y - cv.y;
            float dz = zv.z - cv.z, dw = zv.w - cv.w;
            l = dx * dx + dy * dy + dz * dz + dw * dw;
        }
#pragma unroll
        for (int off = 16; off; off >>= 1)
            l += __shfl_down_sync(0xffffffffu, l, off);
        if (lane == 0) g_tokloss[t] = l;
    }
    __syncthreads();

    int n = threadIdx.x;
    u64 acc[8];
#pragma unroll
    for (int b2 = 0; b2 < 8; ++b2) acc[b2] = 0ULL;

    // depth-12 register prefetch on the W stream (raise LDG MLP)
    const float* Wp = W + (size_t)k0 * H2_ + n;
    float wreg[12];
#pragma unroll
    for (int i = 0; i < 12; ++i) wreg[i] = Wp[(size_t)i * H2_];

    for (int kk0 = 0; kk0 < 256; kk0 += 4) {
#pragma unroll
        for (int i = 0; i < 4; ++i) {
            float wv = wreg[0];
#pragma unroll
            for (int q = 0; q < 11; ++q) wreg[q] = wreg[q + 1];
            int kn = kk0 + 12 + i;
            wreg[11] = (kn < 256) ? Wp[(size_t)kn * H2_] : 0.0f;
            u64 wd = dupf(wv);
            const ulonglong2* dk = (const ulonglong2*)(zs + (kk0 + i) * 16);
            ulonglong2 p0 = dk[0], p1 = dk[1], p2 = dk[2], p3 = dk[3];
            u64 dp[8] = {p0.x, p0.y, p1.x, p1.y, p2.x, p2.y, p3.x, p3.y};
#pragma unroll
            for (int b2 = 0; b2 < 8; ++b2) ffma2(acc[b2], dp[b2], wd);
        }
    }
#pragma unroll
    for (int b2 = 0; b2 < 8; ++b2) {
        float2 f = unpk(acc[b2]);
        g_dpart[blockIdx.x * 4096 + (2*b2)   * H2_ + n] = f.x;
        g_dpart[blockIdx.x * 4096 + (2*b2+1) * H2_ + n] = f.y;
    }
}

// fused: blocks 0-15 finish dec1; block 16 does vq_loss
__global__ void dec1fin_vqloss_kernel(const float* __restrict__ bias, float* __restrict__ out) {
    if (blockIdx.x < 16) {
        int n = blockIdx.x * 256 + threadIdx.x;
        float s = 0.0f;
        for (int c = 0; c < DEC1_CHUNKS; ++c) s += g_dpart[c * 4096 + n];
        g_dvec[n] = fmaxf(s + bias[n & 255], 0.0f);
    } else {
        __shared__ float sb[256];
        float a = 0.0f;
        for (int i = threadIdx.x; i < T_; i += 256) a += g_tokloss[i];
        sb[threadIdx.x] = a;
        __syncthreads();
        for (int s = 128; s > 0; s >>= 1) {
            if (threadIdx.x < s) sb[threadIdx.x] += sb[threadIdx.x + s];
            __syncthreads();
        }
        if (threadIdx.x == 0) out[OUT_VQL] = sb[0] / (float)(T_ * D_);
    }
}

// decoder GEMM2 + softplus — batch-split CTAs (grid 394 x 2, 8 batches each),
// depth-8 float4 register prefetch; twin CTAs share W via L2.
__global__ __launch_bounds__(256, 2) void dec2_kernel(
    const float* __restrict__ W, const float* __restrict__ bias,
    float* __restrict__ out)
{
    __shared__ __align__(16) float ds[H2_ * 8];
    const int bh = blockIdx.y * 8;            // batch base (0 or 8)
    for (int i = threadIdx.x; i < 2048; i += 256) {
        int b = i >> 8, k = i & 255;
        ds[k * 8 + b] = g_dvec[(bh + b) * H2_ + k];
    }
    __syncthreads();

    int n = (blockIdx.x * 256 + threadIdx.x) * 4;
    if (n >= SF_) return;

    u64 acc[4][4];
#pragma unroll
    for (int b2 = 0; b2 < 4; ++b2)
#pragma unroll
        for (int c = 0; c < 4; ++c) acc[b2][c] = 0ULL;

    const float* Wp = W + n;
    float4 wbuf[8];
#pragma unroll
    for (int i = 0; i < 8; ++i) wbuf[i] = *(const float4*)(Wp + (size_t)i * SF_);

    for (int k0 = 0; k0 < H2_; k0 += 8) {
#pragma unroll
        for (int i = 0; i < 8; ++i) {
            float4 w = wbuf[i];
            int kn = k0 + 8 + i;
            if (kn < H2_) wbuf[i] = *(const float4*)(Wp + (size_t)kn * SF_);
            u64 wd[4] = {dupf(w.x), dupf(w.y), dupf(w.z), dupf(w.w)};
            const ulonglong2* dk = (const ulonglong2*)(ds + (k0 + i) * 8);
            ulonglong2 p0 = dk[0], p1 = dk[1];
            u64 dp[4] = {p0.x, p0.y, p1.x, p1.y};
#pragma unroll
            for (int b2 = 0; b2 < 4; ++b2)
#pragma unroll
                for (int c = 0; c < 4; ++c)
                    ffma2(acc[b2][c], dp[b2], wd[c]);
        }
    }

    float4 bb = *(const float4*)(bias + n);
#pragma unroll
    for (int b2 = 0; b2 < 4; ++b2) {
        float2 f0 = unpk(acc[b2][0]);
        float2 f1 = unpk(acc[b2][1]);
        float2 f2 = unpk(acc[b2][2]);
        float2 f3 = unpk(acc[b2][3]);
        float4 v0, v1;
        v0.x = softplusf(f0.x + bb.x);
        v0.y = softplusf(f1.x + bb.y);
        v0.z = softplusf(f2.x + bb.z);
        v0.w = softplusf(f3.x + bb.w);
        v1.x = softplusf(f0.y + bb.x);
        v1.y = softplusf(f1.y + bb.y);
        v1.z = softplusf(f2.y + bb.z);
        v1.w = softplusf(f3.y + bb.w);
        *(float4*)(out + (size_t)(bh + 2*b2)     * SF_ + n) = v0;
        *(float4*)(out + (size_t)(bh + 2*b2 + 1) * SF_ + n) = v1;
    }
}

// ---------------- launch ----------------
#define SYM(var) ({ void* _p; cudaGetSymbolAddress(&_p, var); _p; })

extern "C" void kernel_launch(void* const* d_in, const int* in_sizes, int n_in,
                              void* d_out, int out_size)
{
    const float* x   = (const float*)d_in[0];
    const float* eps = (const float*)d_in[1];
    const float* We1 = (const float*)d_in[2];
    const float* be1 = (const float*)d_in[3];
    const float* We2 = (const float*)d_in[4];
    const float* be2 = (const float*)d_in[5];
    const float* We3 = (const float*)d_in[6];
    const float* be3 = (const float*)d_in[7];
    const float* cb  = (const float*)d_in[8];
    const float* Wd1 = (const float*)d_in[9];
    const float* bd1 = (const float*)d_in[10];
    const float* Wd2 = (const float*)d_in[11];
    const float* bd2 = (const float*)d_in[12];
    float* out = (float*)d_out;

    float *h1  = (float*)SYM(g_h1);
    float *h2  = (float*)SYM(g_h2);
    float *ze  = (float*)SYM(g_ze);
    float *wt1 = (float*)SYM(g_wt1);
    float *wt2 = (float*)SYM(g_wt2);
    float *wt3 = (float*)SYM(g_wt3);

    cudaFuncSetAttribute(mma_gemm<1>, cudaFuncAttributeMaxDynamicSharedMemorySize, SMEM_BYTES);
    cudaFuncSetAttribute(mma_gemm<5>, cudaFuncAttributeMaxDynamicSharedMemorySize, SMEM_BYTES);
    cudaFuncSetAttribute(vq_kernel,   cudaFuncAttributeMaxDynamicSharedMemorySize, SMEM_BYTES);

    // fused prep: 3 transposes + codebook norms
    prep_kernel<<<516, 256>>>(We1, We2, We3, cb);

    // encoder MLP on tensor cores (bf16x3)
    mma_gemm<1><<<dim3(4, 72), 256, SMEM_BYTES>>>(T_, H1_, F_,
        x,  wt1, be1, h1, nullptr, nullptr);
    mma_gemm<1><<<dim3(2, 72), 256, SMEM_BYTES>>>(T_, H2_, H1_,
        h1, wt2, be2, h2, nullptr, nullptr);
    // encoder head: GEMM + bias + reparameterize fused
    mma_gemm<5><<<dim3(1, 72), 256, SMEM_BYTES>>>(T_, ENC_, H2_,
        h2, wt3, be3, nullptr, eps, out);

    // persistent VQ: cross GEMM + running argmin (2 candidates/token)
    vq_kernel<<<dim3(NCB, 72), 256, SMEM_BYTES>>>(ze, cb);

    // decoder: fused VQ-finish + GEMM1 partials, then reduce + dec2
    dec1_vq_kernel<<<DEC1_CHUNKS, 256>>>(Wd1, cb);
    dec1fin_vqloss_kernel<<<17, 256>>>(bd1, out);
    dec2_kernel<<<dim3((SF_ / 4 + 255) / 256, 2), 256>>>(Wd2, bd2, out);
}

// round 16
// speedup vs baseline: 1.1460x; 1.1460x over previous
#include <cuda_runtime.h>
#include <cuda_bf16.h>
#include <math.h>
#include <stdint.h>

// ---------------- problem constants ----------------
#define B_      16
#define S_      576
#define F_      700
#define D_      64
#define KC_     1024
#define T_      (B_*S_)         // 9216 tokens
#define H1_     512
#define H2_     256
#define ENC_    128             // 2*D
#define SF_     (S_*F_)         // 403200
#define SD_     (S_*D_)         // 36864

#define OUT_REC  0
#define OUT_MEAN (B_*SF_)
#define OUT_LV   (OUT_MEAN + T_*D_)
#define OUT_VQL  (OUT_LV + T_*D_)

#define DEC1_CHUNKS 144
#define NCB         2            // candidate blocks (vq grid.x)
#define VQ_CB       4            // codebook col-blocks per vq CTA

typedef unsigned long long u64;
typedef __nv_bfloat16 bf16;

// ---------------- scratch (device globals; no allocation allowed) ----------------
__device__ __align__(256) float g_h1[T_*H1_];
__device__ __align__(256) float g_h2[T_*H2_];
__device__ __align__(256) float g_ze[T_*D_];
__device__ __align__(256) float g_csq[KC_];
__device__ __align__(256) float g_tokloss[T_];
__device__ __align__(256) float g_dpart[DEC1_CHUNKS*16*H2_];
__device__ __align__(256) float g_dvec[16*H2_];
__device__ __align__(256) float g_wt1[H1_*F_];
__device__ __align__(256) float g_wt2[H2_*H1_];
__device__ __align__(256) float g_wt3[ENC_*H2_];
__device__ __align__(256) float g_candD[NCB*T_];
__device__ __align__(256) int   g_candI[NCB*T_];

// ---------------- f32x2 helpers (decoder kernels) ----------------
__device__ __forceinline__ u64 dupf(float a) {
    unsigned r = __float_as_uint(a);
    u64 d;
    asm("mov.b64 %0, {%1, %1};" : "=l"(d) : "r"(r));
    return d;
}
__device__ __forceinline__ void ffma2(u64 &d, u64 a, u64 b) {
    asm("fma.rn.f32x2 %0, %1, %2, %0;" : "+l"(d) : "l"(a), "l"(b));
}
__device__ __forceinline__ float2 unpk(u64 v) {
    unsigned lo, hi;
    asm("mov.b64 {%0, %1}, %2;" : "=r"(lo), "=r"(hi) : "l"(v));
    return make_float2(__uint_as_float(lo), __uint_as_float(hi));
}
__device__ __forceinline__ float softplusf(float x) {
    return fmaxf(x, 0.0f) + log1pf(expf(-fabsf(x)));
}
__device__ __forceinline__ float4 ldcs4(const float* p) {
    float4 v;
    asm volatile("ld.global.cs.v4.f32 {%0,%1,%2,%3}, [%4];"
                 : "=f"(v.x), "=f"(v.y), "=f"(v.z), "=f"(v.w) : "l"(p));
    return v;
}
__device__ __forceinline__ void stcs4(float* p, float4 v) {
    asm volatile("st.global.cs.v4.f32 [%0], {%1,%2,%3,%4};"
                 :: "l"(p), "f"(v.x), "f"(v.y), "f"(v.z), "f"(v.w) : "memory");
}

// ---------------- mma.sync helpers ----------------
__device__ __forceinline__ uint32_t smem_u32(const void* p) {
    uint32_t a;
    asm("{ .reg .u64 t; cvta.to.shared.u64 t, %1; cvt.u32.u64 %0, t; }" : "=r"(a) : "l"(p));
    return a;
}
__device__ __forceinline__ void ldsm4(uint32_t (&r)[4], uint32_t addr) {
    asm volatile("ldmatrix.sync.aligned.m8n8.x4.shared.b16 {%0,%1,%2,%3}, [%4];"
                 : "=r"(r[0]), "=r"(r[1]), "=r"(r[2]), "=r"(r[3]) : "r"(addr));
}
__device__ __forceinline__ void mma_bf16(float (&d)[4], const uint32_t (&a)[4],
                                         uint32_t b0, uint32_t b1) {
    asm volatile("mma.sync.aligned.m16n8k16.row.col.f32.bf16.bf16.f32 "
                 "{%0,%1,%2,%3}, {%4,%5,%6,%7}, {%8,%9}, {%0,%1,%2,%3};"
                 : "+f"(d[0]), "+f"(d[1]), "+f"(d[2]), "+f"(d[3])
                 : "r"(a[0]), "r"(a[1]), "r"(a[2]), "r"(a[3]), "r"(b0), "r"(b1));
}
// split fp32 pair -> packed bf16x2 hi and lo
__device__ __forceinline__ void split2(float x, float y, uint32_t &hi, uint32_t &lo) {
    __nv_bfloat162 h = __floats2bfloat162_rn(x, y);
    float hx = __bfloat162float(h.x), hy = __bfloat162float(h.y);
    __nv_bfloat162 l = __floats2bfloat162_rn(x - hx, y - hy);
    hi = *reinterpret_cast<uint32_t*>(&h);
    lo = *reinterpret_cast<uint32_t*>(&l);
}

// SMEM per stage: 20480 bf16 elems (40960 B): Ah[128][40] | Al +5120 | Bh +10240 | Bl +15360
#define STAGE_E   20480
#define NSTG      3
#define SMEM_BYTES (NSTG * STAGE_E * 2)

// ---------------- bf16x3 tensor-core GEMM, 3-buffer single-sync pipeline ---------
// MODE 1: relu+bias fp32 out.  MODE 5: encoder head — fused bias + reparam epilogue.
template<int MODE>
__global__ __launch_bounds__(256, 1) void mma_gemm(
    int M, int N, int K,
    const float* __restrict__ A, const float* __restrict__ Bt,
    const float* __restrict__ bias, float* __restrict__ C,
    const float* __restrict__ ep, float* __restrict__ outp)
{
    extern __shared__ __align__(16) __nv_bfloat16 sm[];
    const int tid  = threadIdx.x;
    const int wid  = tid >> 5;
    const int lane = tid & 31;
    const int row0 = blockIdx.y * 128;
    const int col0 = blockIdx.x * 128;
    const int NS = (K + 31) >> 5;
    const uint32_t smb = smem_u32(sm);

    float acc[2][8][4];
#pragma unroll
    for (int mt = 0; mt < 2; ++mt)
#pragma unroll
        for (int nt = 0; nt < 8; ++nt)
#pragma unroll
            for (int q = 0; q < 4; ++q) acc[mt][nt][q] = 0.0f;

    const int lrow = tid >> 3;        // 0..31 base row (with +32*i)
    const int lc4  = tid & 7;         // float4 col within BK

    float4 pa[4], pb[4];

    auto fetch = [&](int k0) {
#pragma unroll
        for (int i = 0; i < 4; ++i) {
            int row = lrow + i * 32;
            int kk  = k0 + lc4 * 4;
            if (kk < K) {
                pa[i] = *(const float4*)(A  + (size_t)(row0 + row) * K + kk);
                pb[i] = *(const float4*)(Bt + (size_t)(col0 + row) * K + kk);
            } else {
                pa[i] = make_float4(0.f, 0.f, 0.f, 0.f);
                pb[i] = make_float4(0.f, 0.f, 0.f, 0.f);
            }
        }
    };

    auto store_to = [&](int slot) {
        uint32_t stg = (uint32_t)slot * STAGE_E;
#pragma unroll
        for (int i = 0; i < 4; ++i) {
            int row = lrow + i * 32;
            uint32_t off = stg + row * 40 + lc4 * 4;
            uint32_t h0, l0, h1, l1;
            split2(pa[i].x, pa[i].y, h0, l0);
            split2(pa[i].z, pa[i].w, h1, l1);
            *(uint2*)&sm[off]          = make_uint2(h0, h1);
            *(uint2*)&sm[off + 5120]   = make_uint2(l0, l1);
            split2(pb[i].x, pb[i].y, h0, l0);
            split2(pb[i].z, pb[i].w, h1, l1);
            *(uint2*)&sm[off + 10240]  = make_uint2(h0, h1);
            *(uint2*)&sm[off + 15360]  = make_uint2(l0, l1);
        }
    };

    const int wm = wid >> 1, wn = wid & 1;
    const int arow  = wm * 32 + (lane & 15);
    const int acolB = (lane >> 4) * 16;
    const int brow  = wn * 64 + ((lane >> 4) << 3) + (lane & 7);
    const int bkhB  = ((lane >> 3) & 1) * 16;

    auto compute = [&](int slot) {
        const uint32_t stgB = (uint32_t)slot * (STAGE_E * 2);
#pragma unroll
        for (int ks = 0; ks < 2; ++ks) {
            uint32_t ah[2][4], al[2][4];
#pragma unroll
            for (int mt = 0; mt < 2; ++mt) {
                uint32_t addr = smb + stgB + (uint32_t)(arow + mt * 16) * 80u
                              + (uint32_t)ks * 32u + acolB;
                ldsm4(ah[mt], addr);
                ldsm4(al[mt], addr + 10240u);
            }
            uint32_t bh[8][2], bl[8][2];
#pragma unroll
            for (int p = 0; p < 4; ++p) {
                uint32_t addr = smb + stgB + 20480u + (uint32_t)(brow + p * 16) * 80u
                              + (uint32_t)ks * 32u + bkhB;
                uint32_t r[4];
                ldsm4(r, addr);
                bh[2*p][0] = r[0]; bh[2*p][1] = r[1];
                bh[2*p+1][0] = r[2]; bh[2*p+1][1] = r[3];
                ldsm4(r, addr + 10240u);
                bl[2*p][0] = r[0]; bl[2*p][1] = r[1];
                bl[2*p+1][0] = r[2]; bl[2*p+1][1] = r[3];
            }
#pragma unroll
            for (int mt = 0; mt < 2; ++mt)
#pragma unroll
                for (int nt = 0; nt < 8; ++nt) {
                    mma_bf16(acc[mt][nt], ah[mt], bh[nt][0], bh[nt][1]);
                    mma_bf16(acc[mt][nt], ah[mt], bl[nt][0], bl[nt][1]);
                    mma_bf16(acc[mt][nt], al[mt], bh[nt][0], bh[nt][1]);
                }
        }
    };

    fetch(0);
    store_to(0);
    if (NS > 1) fetch(32);

    int scur = 0, sst = 1;
    for (int s = 0; s < NS; ++s) {
        __syncthreads();
        if (s + 1 < NS) store_to(sst);
        if (s + 2 < NS) fetch((s + 2) * 32);
        compute(scur);
        scur = (scur + 1 == NSTG) ? 0 : scur + 1;
        sst  = (sst  + 1 == NSTG) ? 0 : sst  + 1;
    }

    // ---- epilogue ----
    if (MODE == 5) {
        __syncthreads();
        float* smf = (float*)sm;       // [128][132]
#pragma unroll
        for (int mt = 0; mt < 2; ++mt) {
            int r = wm * 32 + mt * 16 + (lane >> 2);
#pragma unroll
            for (int nt = 0; nt < 8; ++nt) {
                int c = wn * 64 + nt * 8 + (lane & 3) * 2;
                float b0 = bias[c], b1 = bias[c + 1];
                smf[r * 132 + c]           = acc[mt][nt][0] + b0;
                smf[r * 132 + c + 1]       = acc[mt][nt][1] + b1;
                smf[(r + 8) * 132 + c]     = acc[mt][nt][2] + b0;
                smf[(r + 8) * 132 + c + 1] = acc[mt][nt][3] + b1;
            }
        }
        __syncthreads();
#pragma unroll
        for (int it = 0; it < 32; ++it) {
            int idx = it * 256 + tid;          // 0..8191
            int r = idx >> 6, d = idx & 63;
            float m  = smf[r * 132 + d];
            float lv = smf[r * 132 + 64 + d];
            int gi = (row0 + r) * 64 + d;
            float zv = m + expf(0.5f * lv) * ep[gi];
            g_ze[gi] = zv;
            outp[OUT_MEAN + gi] = m;
            outp[OUT_LV + gi]   = lv;
        }
        return;
    }

#pragma unroll
    for (int mt = 0; mt < 2; ++mt) {
        int r = row0 + wm * 32 + mt * 16 + (lane >> 2);
#pragma unroll
        for (int nt = 0; nt < 8; ++nt) {
            int c = col0 + wn * 64 + nt * 8 + (lane & 3) * 2;
            float b0 = bias[c], b1 = bias[c + 1];
            float v0 = fmaxf(acc[mt][nt][0] + b0, 0.0f);
            float v1 = fmaxf(acc[mt][nt][1] + b1, 0.0f);
            float v2 = fmaxf(acc[mt][nt][2] + b0, 0.0f);
            float v3 = fmaxf(acc[mt][nt][3] + b1, 0.0f);
            *(float2*)&C[(size_t)r * N + c]       = make_float2(v0, v1);
            *(float2*)&C[(size_t)(r + 8) * N + c] = make_float2(v2, v3);
        }
    }
}

// ---------------- persistent VQ kernel ----------------
__global__ __launch_bounds__(256, 1) void vq_kernel(
    const float* __restrict__ A, const float* __restrict__ cbk)
{
    extern __shared__ __align__(16) __nv_bfloat16 sm[];
    __shared__ float scsq[KC_];
    __shared__ float sdm[256];
    __shared__ int   sim[256];

    const int tid  = threadIdx.x;
    const int wid  = tid >> 5;
    const int lane = tid & 31;
    const int row0 = blockIdx.y * 128;
    const uint32_t smb = smem_u32(sm);

    for (int i = tid; i < KC_; i += 256) scsq[i] = g_csq[i];

    const int lrow = tid >> 3;
    const int lc4  = tid & 7;

    // ---- load A (z_e) tile: 2 k-stages, hi/lo ----
#pragma unroll
    for (int s2 = 0; s2 < 2; ++s2) {
#pragma unroll
        for (int i = 0; i < 4; ++i) {
            int row = lrow + i * 32;
            float4 v = *(const float4*)(A + (size_t)(row0 + row) * 64 + s2 * 32 + lc4 * 4);
            uint32_t h0, l0, h1, l1;
            split2(v.x, v.y, h0, l0);
            split2(v.z, v.w, h1, l1);
            uint32_t off = s2 * 10240 + row * 40 + lc4 * 4;
            *(uint2*)&sm[off]        = make_uint2(h0, h1);
            *(uint2*)&sm[off + 5120] = make_uint2(l0, l1);
        }
    }

    float4 pb[8];
    auto fetchB = [&](int cb) {
        int colcb = (blockIdx.x * VQ_CB + cb) * 128;
#pragma unroll
        for (int i = 0; i < 4; ++i) {
            int row = colcb + lrow + i * 32;
            pb[i]     = *(const float4*)(cbk + (size_t)row * 64 + lc4 * 4);
            pb[4 + i] = *(const float4*)(cbk + (size_t)row * 64 + 32 + lc4 * 4);
        }
    };
    auto storeB = [&](int buf) {
        uint32_t base = 20480 + (uint32_t)buf * 20480;
#pragma unroll
        for (int s2 = 0; s2 < 2; ++s2) {
#pragma unroll
            for (int i = 0; i < 4; ++i) {
                int row = lrow + i * 32;
                float4 v = pb[s2 * 4 + i];
                uint32_t h0, l0, h1, l1;
                split2(v.x, v.y, h0, l0);
                split2(v.z, v.w, h1, l1);
                uint32_t off = base + s2 * 10240 + row * 40 + lc4 * 4;
                *(uint2*)&sm[off]        = make_uint2(h0, h1);
                *(uint2*)&sm[off + 5120] = make_uint2(l0, l1);
            }
        }
    };

    const int wm = wid >> 1, wn = wid & 1;
    const int arow  = wm * 32 + (lane & 15);
    const int acolB = (lane >> 4) * 16;
    const int brow  = wn * 64 + ((lane >> 4) << 3) + (lane & 7);
    const int bkhB  = ((lane >> 3) & 1) * 16;

    fetchB(0);
    storeB(0);
    __syncthreads();

    float rbD[2][2] = {{3.4e38f, 3.4e38f}, {3.4e38f, 3.4e38f}};
    int   rbI[2][2] = {{0x7fffffff, 0x7fffffff}, {0x7fffffff, 0x7fffffff}};

    int buf = 0;
    for (int cb = 0; cb < VQ_CB; ++cb) {
        if (cb + 1 < VQ_CB) fetchB(cb + 1);

        float acc[2][8][4];
#pragma unroll
        for (int mt = 0; mt < 2; ++mt)
#pragma unroll
            for (int nt = 0; nt < 8; ++nt)
#pragma unroll
                for (int q = 0; q < 4; ++q) acc[mt][nt][q] = 0.0f;

        const uint32_t bbase = 40960u + (uint32_t)buf * 40960u;
#pragma unroll
        for (int s2 = 0; s2 < 2; ++s2) {
            const uint32_t aB = (uint32_t)s2 * 20480u;
            const uint32_t bB = bbase + (uint32_t)s2 * 20480u;
#pragma unroll
            for (int ks = 0; ks < 2; ++ks) {
                uint32_t ah[2][4], al[2][4];
#pragma unroll
                for (int mt = 0; mt < 2; ++mt) {
                    uint32_t addr = smb + aB + (uint32_t)(arow + mt * 16) * 80u
                                  + (uint32_t)ks * 32u + acolB;
                    ldsm4(ah[mt], addr);
                    ldsm4(al[mt], addr + 10240u);
                }
                uint32_t bh[8][2], bl[8][2];
#pragma unroll
                for (int p = 0; p < 4; ++p) {
                    uint32_t addr = smb + bB + (uint32_t)(brow + p * 16) * 80u
                                  + (uint32_t)ks * 32u + bkhB;
                    uint32_t r[4];
                    ldsm4(r, addr);
                    bh[2*p][0] = r[0]; bh[2*p][1] = r[1];
                    bh[2*p+1][0] = r[2]; bh[2*p+1][1] = r[3];
                    ldsm4(r, addr + 10240u);
                    bl[2*p][0] = r[0]; bl[2*p][1] = r[1];
                    bl[2*p+1][0] = r[2]; bl[2*p+1][1] = r[3];
                }
#pragma unroll
                for (int mt = 0; mt < 2; ++mt)
#pragma unroll
                    for (int nt = 0; nt < 8; ++nt) {
                        mma_bf16(acc[mt][nt], ah[mt], bh[nt][0], bh[nt][1]);
                        mma_bf16(acc[mt][nt], ah[mt], bl[nt][0], bl[nt][1]);
                        mma_bf16(acc[mt][nt], al[mt], bh[nt][0], bh[nt][1]);
                    }
            }
        }

        int colcb = (blockIdx.x * VQ_CB + cb) * 128;
#pragma unroll
        for (int mt = 0; mt < 2; ++mt) {
#pragma unroll
            for (int rp = 0; rp < 2; ++rp) {
                float best = 3.4e38f; int bidx = 0;
#pragma unroll
                for (int nt = 0; nt < 8; ++nt) {
                    int cg = colcb + wn * 64 + nt * 8 + (lane & 3) * 2;
                    float d0 = scsq[cg]     - 2.0f * acc[mt][nt][rp * 2 + 0];
                    float d1 = scsq[cg + 1] - 2.0f * acc[mt][nt][rp * 2 + 1];
                    if (d0 < best) { best = d0; bidx = cg;     }
                    if (d1 < best) { best = d1; bidx = cg + 1; }
                }
#pragma unroll
                for (int msk = 1; msk <= 2; msk <<= 1) {
                    float od = __shfl_xor_sync(0xffffffffu, best, msk);
                    int   oi = __shfl_xor_sync(0xffffffffu, bidx, msk);
                    if (od < best || (od == best && oi < bidx)) { best = od; bidx = oi; }
                }
                if (best < rbD[mt][rp] || (best == rbD[mt][rp] && bidx < rbI[mt][rp])) {
                    rbD[mt][rp] = best; rbI[mt][rp] = bidx;
                }
            }
        }

        if (cb + 1 < VQ_CB) {
            __syncthreads();
            storeB(buf ^ 1);
            __syncthreads();
            buf ^= 1;
        }
    }

    if ((lane & 3) == 0) {
#pragma unroll
        for (int mt = 0; mt < 2; ++mt)
#pragma unroll
            for (int rp = 0; rp < 2; ++rp) {
                int rl = wm * 32 + mt * 16 + rp * 8 + (lane >> 2);
                sdm[wn * 128 + rl] = rbD[mt][rp];
                sim[wn * 128 + rl] = rbI[mt][rp];
            }
    }
    __syncthreads();
    if (tid < 128) {
        float d0 = sdm[tid], d1 = sdm[128 + tid];
        int   i0 = sim[tid], i1 = sim[128 + tid];
        bool t1 = (d1 < d0) || (d1 == d0 && i1 < i0);
        g_candD[(size_t)blockIdx.x * T_ + row0 + tid] = t1 ? d1 : d0;
        g_candI[(size_t)blockIdx.x * T_ + row0 + tid] = t1 ? i1 : i0;
    }
}

// ---------------- fused prep: 3 weight transposes + codebook sq norms ------------
__device__ __forceinline__ void transpose_tile(const float* __restrict__ W,
                                               float* __restrict__ Wt,
                                               int K, int N, int kb, int nb, int tid)
{
    __shared__ float tile[32][33];
    int tx = tid & 31, ty = tid >> 5;   // 32 x 8
#pragma unroll
    for (int i = 0; i < 32; i += 8) {
        int k = kb + ty + i, n = nb + tx;
        tile[ty + i][tx] = (k < K && n < N) ? W[(size_t)k * N + n] : 0.0f;
    }
    __syncthreads();
#pragma unroll
    for (int i = 0; i < 32; i += 8) {
        int n = nb + ty + i, k = kb + tx;
        if (n < N && k < K) Wt[(size_t)n * K + k] = tile[tx][ty + i];
    }
}

__global__ void prep_kernel(const float* __restrict__ We1, const float* __restrict__ We2,
                            const float* __restrict__ We3, const float* __restrict__ cb)
{
    int bx = blockIdx.x, tid = threadIdx.x;
    if (bx < 352) {               // W1: 16 x 22 tiles
        transpose_tile(We1, g_wt1, F_,  H1_, (bx >> 4) * 32, (bx & 15) * 32, tid);
    } else if (bx < 480) {        // W2: 8 x 16 tiles
        int b = bx - 352;
        transpose_tile(We2, g_wt2, H1_, H2_, (b >> 3) * 32, (b & 7) * 32, tid);
    } else if (bx < 512) {        // W3: 4 x 8 tiles
        int b = bx - 480;
        transpose_tile(We3, g_wt3, H2_, ENC_, (b >> 2) * 32, (b & 3) * 32, tid);
    } else {                      // csq: 4 blocks x 256 codes
        int k = (bx - 512) * 256 + tid;
        const float4* c = (const float4*)cb + k * 16;
        float s = 0.0f;
#pragma unroll
        for (int i = 0; i < 16; ++i) {
            float4 v = c[i];
            s += v.x * v.x + v.y * v.y + v.z * v.z + v.w * v.w;
        }
        g_csq[k] = s;
    }
}

// ---------------- fused VQ-finish + decoder GEMM1 split-K partials ----------------
// CTA c owns K-chunk [256c, 256c+256) = tokens (b, s in [4c, 4c+4)), 64 tokens.
__global__ __launch_bounds__(256) void dec1_vq_kernel(const float* __restrict__ W,
                                                      const float* __restrict__ cbk)
{
    __shared__ __align__(16) float zs[256 * 16];   // zs[kk*16 + b]
    const int c    = blockIdx.x;
    const int k0   = c * 256;
    const int wid  = threadIdx.x >> 5;
    const int lane = threadIdx.x & 31;

    // 64 tokens, 8 warps x 8 iterations
#pragma unroll
    for (int i = 0; i < 8; ++i) {
        int tt = i * 8 + wid;                 // 0..63
        int b = tt >> 2, j = tt & 3;
        int t = b * S_ + 4 * c + j;

        float d = 3.4e38f; int ix = 0x7fffffff;
        if (lane < NCB) {
            d  = g_candD[(size_t)lane * T_ + t];
            ix = g_candI[(size_t)lane * T_ + t];
        }
        {
            float od = __shfl_down_sync(0xffffffffu, d, 1);
            int   oi = __shfl_down_sync(0xffffffffu, ix, 1);
            if (od < d || (od == d && oi < ix)) { d = od; ix = oi; }
        }
        ix = __shfl_sync(0xffffffffu, ix, 0);

        float l = 0.0f;
        if (lane < 16) {
            float4 cv = ((const float4*)cbk)[ix * 16 + lane];
            float4 zv = ((const float4*)g_ze)[t * 16 + lane];
            int kk = j * 64 + lane * 4;
            zs[(kk + 0) * 16 + b] = cv.x;
            zs[(kk + 1) * 16 + b] = cv.y;
            zs[(kk + 2) * 16 + b] = cv.z;
            zs[(kk + 3) * 16 + b] = cv.w;
            float dx = zv.x - cv.x, dy = zv.y - cv.y;
            float dz = zv.z - cv.z, dw = zv.w - cv.w;
            l = dx * dx + dy * dy + dz * dz + dw * dw;
        }
#pragma unroll
        for (int off = 16; off; off >>= 1)
            l += __shfl_down_sync(0xffffffffu, l, off);
        if (lane == 0) g_tokloss[t] = l;
    }
    __syncthreads();

    int n = threadIdx.x;
    u64 acc[8];
#pragma unroll
    for (int b2 = 0; b2 < 8; ++b2) acc[b2] = 0ULL;

    // depth-12 register prefetch on the W stream (raise LDG MLP)
    const float* Wp = W + (size_t)k0 * H2_ + n;
    float wreg[12];
#pragma unroll
    for (int i = 0; i < 12; ++i) wreg[i] = Wp[(size_t)i * H2_];

    for (int kk0 = 0; kk0 < 256; kk0 += 4) {
#pragma unroll
        for (int i = 0; i < 4; ++i) {
            float wv = wreg[0];
#pragma unroll
            for (int q = 0; q < 11; ++q) wreg[q] = wreg[q + 1];
            int kn = kk0 + 12 + i;
            wreg[11] = (kn < 256) ? Wp[(size_t)kn * H2_] : 0.0f;
            u64 wd = dupf(wv);
            const ulonglong2* dk = (const ulonglong2*)(zs + (kk0 + i) * 16);
            ulonglong2 p0 = dk[0], p1 = dk[1], p2 = dk[2], p3 = dk[3];
            u64 dp[8] = {p0.x, p0.y, p1.x, p1.y, p2.x, p2.y, p3.x, p3.y};
#pragma unroll
            for (int b2 = 0; b2 < 8; ++b2) ffma2(acc[b2], dp[b2], wd);
        }
    }
#pragma unroll
    for (int b2 = 0; b2 < 8; ++b2) {
        float2 f = unpk(acc[b2]);
        g_dpart[blockIdx.x * 4096 + (2*b2)   * H2_ + n] = f.x;
        g_dpart[blockIdx.x * 4096 + (2*b2+1) * H2_ + n] = f.y;
    }
}

// fused: blocks 0-15 finish dec1; block 16 does vq_loss
__global__ void dec1fin_vqloss_kernel(const float* __restrict__ bias, float* __restrict__ out) {
    if (blockIdx.x < 16) {
        int n = blockIdx.x * 256 + threadIdx.x;
        float s = 0.0f;
        for (int c = 0; c < DEC1_CHUNKS; ++c) s += g_dpart[c * 4096 + n];
        g_dvec[n] = fmaxf(s + bias[n & 255], 0.0f);
    } else {
        __shared__ float sb[256];
        float a = 0.0f;
        for (int i = threadIdx.x; i < T_; i += 256) a += g_tokloss[i];
        sb[threadIdx.x] = a;
        __syncthreads();
        for (int s = 128; s > 0; s >>= 1) {
            if (threadIdx.x < s) sb[threadIdx.x] += sb[threadIdx.x + s];
            __syncthreads();
        }
        if (threadIdx.x == 0) out[OUT_VQL] = sb[0] / (float)(T_ * D_);
    }
}

// decoder GEMM2 + softplus — depth-8 float4 streaming prefetch (round-12 config)
__global__ __launch_bounds__(256, 2) void dec2_kernel(
    const float* __restrict__ W, const float* __restrict__ bias,
    float* __restrict__ out)
{
    __shared__ __align__(16) float ds[H2_ * 16];
    for (int i = threadIdx.x; i < 4096; i += 256) {
        int b = i >> 8, k = i & 255;
        ds[k * 16 + b] = g_dvec[i];
    }
    __syncthreads();

    int n = (blockIdx.x * 256 + threadIdx.x) * 4;
    if (n >= SF_) return;

    u64 acc[8][4];
#pragma unroll
    for (int b2 = 0; b2 < 8; ++b2)
#pragma unroll
        for (int c = 0; c < 4; ++c) acc[b2][c] = 0ULL;

    const float* Wp = W + n;
    float4 wbuf[8];
#pragma unroll
    for (int i = 0; i < 8; ++i) wbuf[i] = ldcs4(Wp + (size_t)i * SF_);

    for (int k0 = 0; k0 < H2_; k0 += 8) {
#pragma unroll
        for (int i = 0; i < 8; ++i) {
            float4 w = wbuf[i];
            int kn = k0 + 8 + i;
            if (kn < H2_) wbuf[i] = ldcs4(Wp + (size_t)kn * SF_);
            u64 wd[4] = {dupf(w.x), dupf(w.y), dupf(w.z), dupf(w.w)};
            const ulonglong2* dk = (const ulonglong2*)(ds + (k0 + i) * 16);
            ulonglong2 p0 = dk[0], p1 = dk[1], p2 = dk[2], p3 = dk[3];
            u64 dp[8] = {p0.x, p0.y, p1.x, p1.y, p2.x, p2.y, p3.x, p3.y};
#pragma unroll
            for (int b2 = 0; b2 < 8; ++b2)
#pragma unroll
                for (int c = 0; c < 4; ++c)
                    ffma2(acc[b2][c], dp[b2], wd[c]);
        }
    }

    float4 bb = *(const float4*)(bias + n);
#pragma unroll
    for (int b2 = 0; b2 < 8; ++b2) {
        float2 f0 = unpk(acc[b2][0]);
        float2 f1 = unpk(acc[b2][1]);
        float2 f2 = unpk(acc[b2][2]);
        float2 f3 = unpk(acc[b2][3]);
        float4 v0, v1;
        v0.x = softplusf(f0.x + bb.x);
        v0.y = softplusf(f1.x + bb.y);
        v0.z = softplusf(f2.x + bb.z);
        v0.w = softplusf(f3.x + bb.w);
        v1.x = softplusf(f0.y + bb.x);
        v1.y = softplusf(f1.y + bb.y);
        v1.z = softplusf(f2.y + bb.z);
        v1.w = softplusf(f3.y + bb.w);
        stcs4(out + (size_t)(2*b2)   * SF_ + n, v0);
        stcs4(out + (size_t)(2*b2+1) * SF_ + n, v1);
    }
}

// ---------------- launch ----------------
#define SYM(var) ({ void* _p; cudaGetSymbolAddress(&_p, var); _p; })

extern "C" void kernel_launch(void* const* d_in, const int* in_sizes, int n_in,
                              void* d_out, int out_size)
{
    const float* x   = (const float*)d_in[0];
    const float* eps = (const float*)d_in[1];
    const float* We1 = (const float*)d_in[2];
    const float* be1 = (const float*)d_in[3];
    const float* We2 = (const float*)d_in[4];
    const float* be2 = (const float*)d_in[5];
    const float* We3 = (const float*)d_in[6];
    const float* be3 = (const float*)d_in[7];
    const float* cb  = (const float*)d_in[8];
    const float* Wd1 = (const float*)d_in[9];
    const float* bd1 = (const float*)d_in[10];
    const float* Wd2 = (const float*)d_in[11];
    const float* bd2 = (const float*)d_in[12];
    float* out = (float*)d_out;

    float *h1  = (float*)SYM(g_h1);
    float *h2  = (float*)SYM(g_h2);
    float *ze  = (float*)SYM(g_ze);
    float *wt1 = (float*)SYM(g_wt1);
    float *wt2 = (float*)SYM(g_wt2);
    float *wt3 = (float*)SYM(g_wt3);

    cudaFuncSetAttribute(mma_gemm<1>, cudaFuncAttributeMaxDynamicSharedMemorySize, SMEM_BYTES);
    cudaFuncSetAttribute(mma_gemm<5>, cudaFuncAttributeMaxDynamicSharedMemorySize, SMEM_BYTES);
    cudaFuncSetAttribute(vq_kernel,   cudaFuncAttributeMaxDynamicSharedMemorySize, SMEM_BYTES);

    // fused prep: 3 transposes + codebook norms
    prep_kernel<<<516, 256>>>(We1, We2, We3, cb);

    // encoder MLP on tensor cores (bf16x3)
    mma_gemm<1><<<dim3(4, 72), 256, SMEM_BYTES>>>(T_, H1_, F_,
        x,  wt1, be1, h1, nullptr, nullptr);
    mma_gemm<1><<<dim3(2, 72), 256, SMEM_BYTES>>>(T_, H2_, H1_,
        h1, wt2, be2, h2, nullptr, nullptr);
    // encoder head: GEMM + bias + reparameterize fused
    mma_gemm<5><<<dim3(1, 72), 256, SMEM_BYTES>>>(T_, ENC_, H2_,
        h2, wt3, be3, nullptr, eps, out);

    // persistent VQ: cross GEMM + running argmin (2 candidates/token)
    vq_kernel<<<dim3(NCB, 72), 256, SMEM_BYTES>>>(ze, cb);

    // decoder: fused VQ-finish + GEMM1 partials, then reduce + dec2
    dec1_vq_kernel<<<DEC1_CHUNKS, 256>>>(Wd1, cb);
    dec1fin_vqloss_kernel<<<17, 256>>>(bd1, out);
    dec2_kernel<<<(SF_ / 4 + 255) / 256, 256>>>(Wd2, bd2, out);
}